// round 5
// baseline (speedup 1.0000x reference)
#include <cuda_runtime.h>
#include <math.h>

#define DD 512
#define PP 36
#define RS 37                       // row stride: 36 data + mean in pad slot
#define TILE_F (PP*DD)              // 18432 floats per gmem tile
#define SLOT_F (DD*RS)              // 18944 floats per smem slot
#define NT 512
#define EPSN 1e-12f
#define SCALE_CLS 7.0f

// SMEM float offsets
#define SCO   (3*SLOT_F)            // selection scores [72] (pad 80)
#define NNO   (SCO + 80)            // per-position norms [72]
#define WWO   (NNO + 80)            // fuse weights [72]
#define REDA  (WWO + 80)            // stage-A reduction scratch [48]
#define REDD  (REDA + 48)           // final reduction scratch [48]
#define SMEMF (REDD + 48)
#define SMEMB (SMEMF * 4)           // 228,672 B

__device__ __forceinline__ float warp_sum(float v) {
#pragma unroll
    for (int o = 16; o > 0; o >>= 1) v += __shfl_down_sync(0xffffffffu, v, o);
    return v;
}

// load one tensor-tile row (d) into 9 float4 registers
__device__ __forceinline__ void ldg_tile(int t, const float* __restrict__ ftest,
                                         const float* __restrict__ ftrain,
                                         int d, float4* pre) {
    const float* base = (t & 1) ? ftrain : ftest;
    const float4* s4 = (const float4*)(base + (size_t)(t >> 1) * TILE_F) + d * 9;
#pragma unroll
    for (int k = 0; k < 9; k++) pre[k] = s4[k];
}

// store row into slot (stride-37, conflict-free) + spatial mean into pad
__device__ __forceinline__ void sts_tile(float* slot, int d, const float4* pre) {
    float* row = slot + d * RS;
    float s = 0.f;
#pragma unroll
    for (int k = 0; k < 9; k++) {
        row[4*k+0] = pre[k].x; row[4*k+1] = pre[k].y;
        row[4*k+2] = pre[k].z; row[4*k+3] = pre[k].w;
        s += pre[k].x + pre[k].y + pre[k].z + pre[k].w;
    }
    row[PP] = s * (1.0f / (float)PP);
}

__global__ __launch_bounds__(NT, 1)
void fused_region_score_ring(const float* __restrict__ ftrain,
                             const float* __restrict__ ftest,
                             const int*   __restrict__ Kp,
                             float* __restrict__ out,
                             int groups, int halfOut)
{
    extern __shared__ float sm[];
    float* redA = sm + REDA;
    float* redD = sm + REDD;

    const int tid  = threadIdx.x;
    const int lane = tid & 31;
    const int wid  = tid >> 5;          // 0..15 (16 warps)
    const int d    = tid;
    const int K    = Kp[0];

    // contiguous group partition per CTA
    const int nc = gridDim.x;
    const int q  = groups / nc, r = groups % nc;
    const int gbeg = blockIdx.x * q + min(blockIdx.x, r);
    const int gend = gbeg + q + (blockIdx.x < r ? 1 : 0);
    if (gbeg >= gend) return;
    const int tlim = 2 * gend;

    float4 preA[9], preB[9];

    // ---- prologue: stage tiles 2gb, 2gb+1; prefetch 2gb+2, 2gb+3 ----------
    {
        const int t0 = 2 * gbeg;
        ldg_tile(t0,     ftest, ftrain, d, preA);
        sts_tile(sm + (t0 % 3) * SLOT_F, d, preA);
        ldg_tile(t0 + 1, ftest, ftrain, d, preA);
        sts_tile(sm + ((t0 + 1) % 3) * SLOT_F, d, preA);
        if (t0 + 2 < tlim) ldg_tile(t0 + 2, ftest, ftrain, d, preA);
        if (t0 + 3 < tlim) ldg_tile(t0 + 3, ftest, ftrain, d, preB);
    }
    __syncthreads();

    for (int g = gbeg; g < gend; g++) {
        const float* slotA = sm + ((2 * g)     % 3) * SLOT_F;   // test tile
        const float* slotB = sm + ((2 * g + 1) % 3) * SLOT_F;   // train tile

        // ---- stage A partials: global mean-score terms ---------------------
        {
            float mt = slotA[d * RS + PP];
            float mr = slotB[d * RS + PP];
            float a = warp_sum(mt * mr);
            float b = warp_sum(mt * mt);
            float c = warp_sum(mr * mr);
            if (lane == 0) { redA[wid] = a; redA[16 + wid] = b; redA[32 + wid] = c; }
        }

        // ---- stage B: per-position norm + selection score (72 jobs, 16 warps)
#pragma unroll
        for (int rr = 0; rr < 5; rr++) {
            if (rr == 4 && wid >= 8) break;
            const int j    = wid + 16 * rr;          // 0..71
            const int tens = (j >= PP) ? 1 : 0;
            const int p    = j - PP * tens;
            const float* X = tens ? slotB : slotA;
            const float* M = tens ? slotA : slotB;   // other tensor's mean (pad col)
            float a2 = 0.f, ta = 0.f;
#pragma unroll
            for (int i = 0; i < DD / 32; i++) {
                const int dd = lane + 32 * i;
                float a = X[dd * RS + p];
                float m = M[dd * RS + PP];
                a2 += a * a;
                ta += a * m;
            }
            a2 = warp_sum(a2);
            ta = warp_sum(ta);
            if (lane == 0) {
                float n = fmaxf(sqrtf(a2), EPSN);
                sm[NNO + j] = n;
                sm[SCO + j] = ta / n;   // positive constant factors cancel in ranking
            }
        }
        __syncthreads();   // s1: SC/NN + redA published

        // ---- stage A final: global score -----------------------------------
        if (wid == 0) {
            float a = (lane < 16) ? redA[lane]      : 0.f;
            float b = (lane < 16) ? redA[16 + lane] : 0.f;
            float c = (lane < 16) ? redA[32 + lane] : 0.f;
            a = warp_sum(a); b = warp_sum(b); c = warp_sum(c);
            if (lane == 0) {
                float den = fmaxf(sqrtf(b), EPSN) * fmaxf(sqrtf(c), EPSN);
                out[g] = SCALE_CLS * a / den;
            }
        }

        // ---- stage C: top-K via rank counting ------------------------------
        if (tid < 2 * PP) {
            const int tens = (tid >= PP) ? 1 : 0;
            const int p    = tid - PP * tens;
            const int b0   = PP * tens;
            const float sv = sm[SCO + tid];
            int rank = 0;
#pragma unroll
            for (int qq = 0; qq < PP; qq++) {
                float o = sm[SCO + b0 + qq];
                rank += (o > sv) || (o == sv && qq < p);  // lower index wins ties
            }
            sm[WWO + tid] = (rank < K) ? (1.0f / sm[NNO + tid]) : 0.0f;
        }
        __syncthreads();   // s2: weights published

        // ---- stage D: fused vectors (per-thread d) --------------------------
        float u = 0.f, v = 0.f;
        {
            const float* rowA = slotA + d * RS;
            const float* rowB = slotB + d * RS;
#pragma unroll
            for (int p = 0; p < PP; p++) {
                u += rowA[p] * sm[WWO + p];
                v += rowB[p] * sm[WWO + PP + p];
            }
        }
        __syncthreads();   // s3: slot reads complete -> slots reusable

        // ---- pipeline: store prefetched tiles, issue next LDGs --------------
        {
            const int t2 = 2 * g + 2, t3 = 2 * g + 3;
            if (t2 < tlim) sts_tile(sm + (t2 % 3) * SLOT_F, d, preA);
            if (t3 < tlim) sts_tile(sm + (t3 % 3) * SLOT_F, d, preB);
            const int t4 = 2 * g + 4, t5 = 2 * g + 5;
            if (t4 < tlim) ldg_tile(t4, ftest, ftrain, d, preA);
            if (t5 < tlim) ldg_tile(t5, ftest, ftrain, d, preB);
        }

        // ---- final score partials -------------------------------------------
        {
            float a = warp_sum(u * v);
            float b = warp_sum(u * u);
            float c = warp_sum(v * v);
            if (lane == 0) { redD[wid] = a; redD[16 + wid] = b; redD[32 + wid] = c; }
        }
        __syncthreads();   // s4: redD + new tiles published for next iteration

        if (wid == 0) {
            float a = (lane < 16) ? redD[lane]      : 0.f;
            float b = (lane < 16) ? redD[16 + lane] : 0.f;
            float c = (lane < 16) ? redD[32 + lane] : 0.f;
            a = warp_sum(a); b = warp_sum(b); c = warp_sum(c);
            if (lane == 0) {
                float den = fmaxf(sqrtf(b), EPSN) * fmaxf(sqrtf(c), EPSN);
                out[halfOut + g] = SCALE_CLS * a / den;
            }
        }
        // wid0's redD reads precede its arrival at next iteration's s1; other
        // warps rewrite redD only after next s3 -> ordered, no extra sync.
    }
}

extern "C" void kernel_launch(void* const* d_in, const int* in_sizes, int n_in,
                              void* d_out, int out_size)
{
    const float* ftrain = (const float*)d_in[0];
    const float* ftest  = (const float*)d_in[1];
    const int*   Kp     = (const int*)d_in[2];
    float* out = (float*)d_out;

    const int groups  = in_sizes[0] / (DD * PP);   // 1500
    const int halfOut = out_size / 2;              // 1500

    cudaFuncSetAttribute(fused_region_score_ring,
                         cudaFuncAttributeMaxDynamicSharedMemorySize, SMEMB);
    fused_region_score_ring<<<148, NT, SMEMB>>>(ftrain, ftest, Kp, out,
                                                groups, halfOut);
}

// round 6
// speedup vs baseline: 1.7728x; 1.7728x over previous
#include <cuda_runtime.h>
#include <math.h>

#define DD 512
#define PP 36
#define PS 37          // padded SMEM row stride: conflict-free row & column access
#define NTHREADS 512
#define EPSN 1e-12f
#define SCALE_CLS 7.0f
#define TILE_F (DD*PP)               // 18432 floats per gmem tile
#define TILE_BYTES (TILE_F*4)        // 73728 B
#define LINES_PER_TILE (TILE_BYTES/128)   // 576

// SMEM layout (floats)
#define ST_OFF     0
#define SR_OFF     (DD*PS)
#define MT_OFF     (2*DD*PS)
#define MR_OFF     (MT_OFF + DD)
#define NT_OFF     (MR_OFF + DD)
#define NR_OFF     (NT_OFF + 40)
#define STE_OFF    (NR_OFF + 40)
#define STR_OFF    (STE_OFF + 40)
#define WT_OFF     (STR_OFF + 40)
#define WR_OFF     (WT_OFF + 40)
#define RED_OFF    (WR_OFF + 40)
#define SMEM_FLOATS (RED_OFF + 64)
#define SMEM_BYTES  (SMEM_FLOATS * 4)   // ~156.9 KB

__device__ __forceinline__ float warp_sum(float v) {
#pragma unroll
    for (int o = 16; o > 0; o >>= 1) v += __shfl_down_sync(0xffffffffu, v, o);
    return v;
}

__device__ __forceinline__ void l2_prefetch(const void* p) {
    asm volatile("prefetch.global.L2 [%0];" :: "l"(p));
}

__global__ __launch_bounds__(NTHREADS, 1)
void fused_region_score_l2p(const float* __restrict__ ftrain,
                            const float* __restrict__ ftest,
                            const int*   __restrict__ Kp,
                            float* __restrict__ out,
                            int groups, int halfOut)
{
    extern __shared__ float sm[];
    float* st     = sm + ST_OFF;
    float* sr     = sm + SR_OFF;
    float* mean_t = sm + MT_OFF;
    float* mean_r = sm + MR_OFF;
    float* nt     = sm + NT_OFF;
    float* nr     = sm + NR_OFF;
    float* s_te   = sm + STE_OFF;
    float* s_tr   = sm + STR_OFF;
    float* wt     = sm + WT_OFF;
    float* wr     = sm + WR_OFF;
    float* red    = sm + RED_OFF;

    const int tid  = threadIdx.x;
    const int lane = tid & 31;
    const int wid  = tid >> 5;
    const int K    = Kp[0];

    // contiguous group range per CTA
    const int nc = gridDim.x;
    const int q  = groups / nc, r = groups % nc;
    const int gbeg = blockIdx.x * q + min(blockIdx.x, r);
    const int gend = gbeg + q + (blockIdx.x < r ? 1 : 0);

    // prefetch the FIRST group so even iteration 0 reads mostly from L2
    if (gbeg < gend) {
        const char* bt = (const char*)(ftest  + (size_t)gbeg * TILE_F);
        const char* br = (const char*)(ftrain + (size_t)gbeg * TILE_F);
        for (int j = tid; j < LINES_PER_TILE; j += NTHREADS) {
            l2_prefetch(bt + j * 128);
            l2_prefetch(br + j * 128);
        }
    }

    for (int g = gbeg; g < gend; g++) {
        // ---------------- load tiles (from L2 if prefetch landed) -----------
        const float4* gt = (const float4*)(ftest  + (size_t)g * TILE_F);
        const float4* gr = (const float4*)(ftrain + (size_t)g * TILE_F);
#pragma unroll
        for (int k = 0; k < 9; k++) {
            int j = tid + k * NTHREADS;          // 0..4607
            float4 a = gt[j];
            float4 b = gr[j];
            int d = j / 9;
            int p = (j - d * 9) * 4;
            int s = d * PS + p;
            st[s] = a.x; st[s+1] = a.y; st[s+2] = a.z; st[s+3] = a.w;
            sr[s] = b.x; sr[s+1] = b.y; sr[s+2] = b.z; sr[s+3] = b.w;
        }

        // ---------------- prefetch next group into L2 (fire-and-forget) -----
        if (g + 1 < gend) {
            const char* bt = (const char*)(ftest  + (size_t)(g + 1) * TILE_F);
            const char* br = (const char*)(ftrain + (size_t)(g + 1) * TILE_F);
#pragma unroll
            for (int k = 0; k < 2; k++) {
                int j = tid + k * NTHREADS;      // 0..1023 of 576 lines each
                if (j < LINES_PER_TILE) {
                    l2_prefetch(bt + j * 128);
                    l2_prefetch(br + j * 128);
                }
            }
            // remaining lines 1024..1151 handled by first 128 threads
            if (tid < LINES_PER_TILE - 1024 + 512) { /* no-op guard simplification */ }
            {
                int j = tid + 2 * NTHREADS;
                if (j < LINES_PER_TILE) {
                    l2_prefetch(bt + j * 128);
                    l2_prefetch(br + j * 128);
                }
            }
        }
        __syncthreads();

        // ---------------- stage A: spatial means + mean statistics ----------
        {
            const int d = tid;
            const float* rt = st + d * PS;
            const float* rr = sr + d * PS;
            float sa = 0.f, sb = 0.f;
#pragma unroll
            for (int p = 0; p < PP; p++) { sa += rt[p]; sb += rr[p]; }
            float mt = sa * (1.0f / PP);
            float mr = sb * (1.0f / PP);
            mean_t[d] = mt;
            mean_r[d] = mr;
            float mm  = warp_sum(mt * mr);
            float mt2 = warp_sum(mt * mt);
            float mr2 = warp_sum(mr * mr);
            if (lane == 0) { red[wid] = mm; red[16 + wid] = mt2; red[32 + wid] = mr2; }
        }
        __syncthreads();
        if (wid == 0) {
            float a = (lane < 16) ? red[lane]      : 0.f;
            float b = (lane < 16) ? red[16 + lane] : 0.f;
            float c = (lane < 16) ? red[32 + lane] : 0.f;
            a = warp_sum(a); b = warp_sum(b); c = warp_sum(c);
            if (lane == 0) {
                float denom = fmaxf(sqrtf(b), EPSN) * fmaxf(sqrtf(c), EPSN);
                out[g] = SCALE_CLS * a / denom;
            }
        }
        __syncthreads();   // means visible to stage B

        // ---------------- stage B: per-position norms + selection scores ----
        for (int p = wid; p < PP; p += 16) {
            float a2 = 0.f, b2 = 0.f, ta = 0.f, tb = 0.f;
#pragma unroll
            for (int i = 0; i < DD / 32; i++) {
                int d = lane + 32 * i;
                float a = st[d * PS + p];
                float b = sr[d * PS + p];
                a2 += a * a;
                b2 += b * b;
                ta += a * mean_r[d];
                tb += b * mean_t[d];
            }
            a2 = warp_sum(a2); b2 = warp_sum(b2);
            ta = warp_sum(ta); tb = warp_sum(tb);
            if (lane == 0) {
                float na = fmaxf(sqrtf(a2), EPSN);
                float nb = fmaxf(sqrtf(b2), EPSN);
                nt[p] = na;
                nr[p] = nb;
                s_te[p] = ta / na;   // positive constant factors cancel in ranking
                s_tr[p] = tb / nb;
            }
        }
        __syncthreads();

        // ---------------- stage C: top-K via rank counting ------------------
        if (tid < PP) {
            const int p = tid;
            float sv = s_te[p];
            int rank = 0;
#pragma unroll
            for (int qq = 0; qq < PP; qq++) {
                float o = s_te[qq];
                rank += (o > sv) || (o == sv && qq < p);   // lower index wins ties
            }
            wt[p] = (rank < K) ? (1.0f / nt[p]) : 0.0f;

            sv = s_tr[p];
            rank = 0;
#pragma unroll
            for (int qq = 0; qq < PP; qq++) {
                float o = s_tr[qq];
                rank += (o > sv) || (o == sv && qq < p);
            }
            wr[p] = (rank < K) ? (1.0f / nr[p]) : 0.0f;
        }
        __syncthreads();

        // ---------------- stage D: fused features + final score -------------
        {
            const int d = tid;
            const float* rt = st + d * PS;
            const float* rr = sr + d * PS;
            float u = 0.f, v = 0.f;
#pragma unroll
            for (int p = 0; p < PP; p++) {
                u += rt[p] * wt[p];
                v += rr[p] * wr[p];
            }
            float uu = warp_sum(u * u);
            float vv = warp_sum(v * v);
            float uv = warp_sum(u * v);
            if (lane == 0) { red[wid] = uv; red[16 + wid] = uu; red[32 + wid] = vv; }
        }
        __syncthreads();
        if (wid == 0) {
            float a = (lane < 16) ? red[lane]      : 0.f;
            float b = (lane < 16) ? red[16 + lane] : 0.f;
            float c = (lane < 16) ? red[32 + lane] : 0.f;
            a = warp_sum(a); b = warp_sum(b); c = warp_sum(c);
            if (lane == 0) {
                float denom = fmaxf(sqrtf(b), EPSN) * fmaxf(sqrtf(c), EPSN);
                out[halfOut + g] = SCALE_CLS * a / denom;
            }
        }
        __syncthreads();   // red safe + tile reads done before next load phase
    }
}

extern "C" void kernel_launch(void* const* d_in, const int* in_sizes, int n_in,
                              void* d_out, int out_size)
{
    const float* ftrain = (const float*)d_in[0];
    const float* ftest  = (const float*)d_in[1];
    const int*   Kp     = (const int*)d_in[2];
    float* out = (float*)d_out;

    const int groups  = in_sizes[0] / (DD * PP);   // 1500
    const int halfOut = out_size / 2;              // 1500

    cudaFuncSetAttribute(fused_region_score_l2p,
                         cudaFuncAttributeMaxDynamicSharedMemorySize, SMEM_BYTES);
    fused_region_score_l2p<<<148, NTHREADS, SMEM_BYTES>>>(ftrain, ftest, Kp, out,
                                                          groups, halfOut);
}